// round 2
// baseline (speedup 1.0000x reference)
#include <cuda_runtime.h>
#include <math_constants.h>

// ---------------------------------------------------------------------------
// CNNTest: graph conv (1->32) -> graph conv (32->64) -> FC(64->512) -> softmax
// V = 100000, N = 32 neighbors.
//
// Pipeline:
//   K1: h[v]   = mean_j relu(conv_k3(vp[nb1[v,:]]))           [V]
//   K2: f1[v,o]= sum_k hshift[v,k]*w1[o,k] + b1[o]            [V,32]
//   K3: h2[v,c]= mean_j relu(conv_k3_j(f1[nb2[v,j],c]))       [V,32]
//   Kpre: Wcomb[96,512] = einsum(w2[o,c,k], wfc[p,o])  (fold conv2 into FC)
//         bcomb[512]    = wfc @ b2 + bfc
//   K4: logits[v,p] = sum_{k3,c} h2[v-1+k3,c] * Wcomb[k3*32+c, p] + bcomb[p]
//       out = softmax(logits)  -- fused GEMM + bias + softmax + store
// ---------------------------------------------------------------------------

#define V_MAX 100352   // a bit over 100000 for safety
#define NNB   32

__device__ float g_h [V_MAX];
__device__ float g_f1[V_MAX * 32];
__device__ float g_h2[V_MAX * 32];
__device__ float g_Wc[96 * 512];
__device__ float g_bc[512];

// --------------------------- K1: first graph conv (to scalar h) ------------
__global__ void k_h(const float* __restrict__ vp, const int* __restrict__ nb1,
                    const float* __restrict__ wv1, const float* __restrict__ bv1,
                    int V) {
    int t = blockIdx.x * blockDim.x + threadIdx.x;
    int v = t >> 5;
    int j = t & 31;
    if (v >= V) return;
    float w0 = wv1[0], w1c = wv1[1], w2c = wv1[2], b = bv1[0];

    int   idx = nb1[v * NNB + j];
    float g   = vp[idx];
    float gm  = __shfl_up_sync(0xffffffffu, g, 1);
    float gp  = __shfl_down_sync(0xffffffffu, g, 1);
    if (j == 0)  gm = 0.f;
    if (j == 31) gp = 0.f;
    float c = fmaf(w0, gm, fmaf(w1c, g, fmaf(w2c, gp, b)));
    float r = fmaxf(c, 0.f);
#pragma unroll
    for (int s = 16; s > 0; s >>= 1)
        r += __shfl_xor_sync(0xffffffffu, r, s);
    if (j == 0) g_h[v] = r * (1.f / 32.f);
}

// --------------------------- K2: vertex conv 1 -> 32 channels --------------
__global__ void k_f1(const float* __restrict__ w1, const float* __restrict__ b1,
                     int V) {
    int t = blockIdx.x * blockDim.x + threadIdx.x;
    if (t >= V * 32) return;
    int v = t >> 5;
    int o = t & 31;
    float hm = (v > 0)     ? g_h[v - 1] : 0.f;
    float h0 = g_h[v];
    float hp = (v < V - 1) ? g_h[v + 1] : 0.f;
    g_f1[t] = fmaf(hm, w1[o * 3 + 0],
              fmaf(h0, w1[o * 3 + 1],
              fmaf(hp, w1[o * 3 + 2], b1[o])));
}

// --------------------------- K3: second graph conv (neighbor axis) ---------
// One warp per vertex, one lane per channel. 32 coalesced 128B row gathers
// of f1 (L2-resident, 12.8MB), fully unrolled for MLP.
__global__ void k_h2(const int* __restrict__ nb2,
                     const float* __restrict__ wv2, const float* __restrict__ bv2,
                     int V) {
    int t = blockIdx.x * blockDim.x + threadIdx.x;
    int v = t >> 5;
    int c = t & 31;
    if (v >= V) return;
    float w0 = wv2[0], w1c = wv2[1], w2c = wv2[2], b = bv2[0];

    int myidx = nb2[v * NNB + c];
    float g[32];
#pragma unroll
    for (int j = 0; j < 32; j++) {
        int ij = __shfl_sync(0xffffffffu, myidx, j);
        g[j] = g_f1[ij * 32 + c];
    }
    float acc = 0.f;
#pragma unroll
    for (int j = 0; j < 32; j++) {
        float gm = (j > 0)  ? g[j - 1] : 0.f;
        float gp = (j < 31) ? g[j + 1] : 0.f;
        acc += fmaxf(fmaf(w0, gm, fmaf(w1c, g[j], fmaf(w2c, gp, b))), 0.f);
    }
    g_h2[v * 32 + c] = acc * (1.f / 32.f);
}

// --------------------------- Kpre: fold w2 into wfc ------------------------
// Wcomb[K=k3*32+c][p] = sum_o w2[o,c,k3] * wfc[p,o];  bcomb[p]=bfc[p]+wfc@b2
__global__ void k_pre(const float* __restrict__ w2, const float* __restrict__ wfc,
                      const float* __restrict__ b2, const float* __restrict__ bfc) {
    int p = threadIdx.x;       // 0..511
    int blk = blockIdx.x;      // 0..96
    if (blk < 96) {
        int k3 = blk >> 5;
        int c  = blk & 31;
        float s = 0.f;
#pragma unroll
        for (int o = 0; o < 64; o++)
            s = fmaf(w2[o * 96 + c * 3 + k3], wfc[p * 64 + o], s);
        g_Wc[blk * 512 + p] = s;
    } else {
        float s = bfc[p];
#pragma unroll
        for (int o = 0; o < 64; o++)
            s = fmaf(b2[o], wfc[p * 64 + o], s);
        g_bc[p] = s;
    }
}

// --------------------------- K4: fused GEMM + bias + softmax ---------------
// Block: 256 threads, 32 vertices. Output tile 32x512.
// Warp w owns rows w*4..w*4+3; lane c owns cols {c + 32*j, j=0..15}.
// A panel (96 x 32, stride-36 padded) in smem; B (Wcomb, 196KB) read via
// __ldg — L1-resident after first CTA on each SM (L1 persists across CTAs).
__global__ void __launch_bounds__(256, 2)
k_out(float* __restrict__ out, int V) {
    __shared__ float As[96 * 36];
    int tid = threadIdx.x;
    int wp  = tid >> 5;
    int ln  = tid & 31;
    int v0  = blockIdx.x * 32;

    // Build A panel: As[K][v] = h2[v0+v-1+k3][c], K = k3*32 + c
    for (int i = tid; i < 96 * 32; i += 256) {
        int K  = i % 96;
        int v  = i / 96;
        int k3 = K >> 5;
        int ch = K & 31;
        int row = v0 + v - 1 + k3;
        float val = (row >= 0 && row < V) ? g_h2[row * 32 + ch] : 0.f;
        As[K * 36 + v] = val;
    }
    __syncthreads();

    float acc[4][16];
#pragma unroll
    for (int i = 0; i < 4; i++)
#pragma unroll
        for (int j = 0; j < 16; j++) acc[i][j] = 0.f;

    const float* __restrict__ Wc = g_Wc;
#pragma unroll 2
    for (int k = 0; k < 96; k++) {
        float4 a = *(const float4*)&As[k * 36 + wp * 4];
        const float* br = Wc + k * 512 + ln;
        float bv[16];
#pragma unroll
        for (int j = 0; j < 16; j++) bv[j] = __ldg(br + j * 32);
#pragma unroll
        for (int j = 0; j < 16; j++) {
            acc[0][j] = fmaf(a.x, bv[j], acc[0][j]);
            acc[1][j] = fmaf(a.y, bv[j], acc[1][j]);
            acc[2][j] = fmaf(a.z, bv[j], acc[2][j]);
            acc[3][j] = fmaf(a.w, bv[j], acc[3][j]);
        }
    }

    // bias
    float bb[16];
#pragma unroll
    for (int j = 0; j < 16; j++) bb[j] = __ldg(&g_bc[ln + 32 * j]);

    // per-row softmax: each row lives entirely in one warp (16 vals/lane)
#pragma unroll
    for (int i = 0; i < 4; i++) {
        int v = v0 + wp * 4 + i;
        float m = -CUDART_INF_F;
#pragma unroll
        for (int j = 0; j < 16; j++) {
            acc[i][j] += bb[j];
            m = fmaxf(m, acc[i][j]);
        }
#pragma unroll
        for (int s = 16; s > 0; s >>= 1)
            m = fmaxf(m, __shfl_xor_sync(0xffffffffu, m, s));
        float sum = 0.f;
#pragma unroll
        for (int j = 0; j < 16; j++) {
            acc[i][j] = __expf(acc[i][j] - m);
            sum += acc[i][j];
        }
#pragma unroll
        for (int s = 16; s > 0; s >>= 1)
            sum += __shfl_xor_sync(0xffffffffu, sum, s);
        float inv = __fdividef(1.f, sum);
        if (v < V) {
            float* orow = out + (size_t)v * 512;
#pragma unroll
            for (int j = 0; j < 16; j++)
                orow[ln + 32 * j] = acc[i][j] * inv;
        }
    }
}

// ---------------------------------------------------------------------------
extern "C" void kernel_launch(void* const* d_in, const int* in_sizes, int n_in,
                              void* d_out, int out_size) {
    const float* vp  = (const float*)d_in[0];
    const int*   nb1 = (const int*)  d_in[1];
    const int*   nb2 = (const int*)  d_in[2];
    const float* wv1 = (const float*)d_in[3];
    const float* bv1 = (const float*)d_in[4];
    const float* w1  = (const float*)d_in[5];
    const float* b1  = (const float*)d_in[6];
    const float* wv2 = (const float*)d_in[7];
    const float* bv2 = (const float*)d_in[8];
    const float* w2  = (const float*)d_in[9];
    const float* b2  = (const float*)d_in[10];
    const float* wfc = (const float*)d_in[11];
    const float* bfc = (const float*)d_in[12];
    float* out = (float*)d_out;

    int V = in_sizes[0];
    if (V > V_MAX) V = V_MAX;

    int t32   = V * 32;
    int nblk  = (t32 + 255) / 256;

    k_pre<<<97, 512>>>(w2, wfc, b2, bfc);
    k_h  <<<nblk, 256>>>(vp, nb1, wv1, bv1, V);
    k_f1 <<<nblk, 256>>>(w1, b1, V);
    k_h2 <<<nblk, 256>>>(nb2, wv2, bv2, V);
    k_out<<<(V + 31) / 32, 256>>>(out, V);
}